// round 3
// baseline (speedup 1.0000x reference)
#include <cuda_runtime.h>
#include <math.h>

#define B_  64
#define T_  512
#define IN_ 1024
#define H_  1024
#define L_  5

#define NBLK 128   // persistent CTAs (<=148 so all co-resident at 1 CTA/SM)

// Static device scratch (sanctioned workaround for no-alloc rule):
// g_xw: precomputed [whx|wtx] for all (t,b), time-major: g_xw[(t*B + b)*2H + j]
__device__ float g_xw[(size_t)B_ * T_ * 2 * H_];   // 256 MB
// double-buffered recurrent state s: [2][B][H]
__device__ float g_state[2][B_ * H_];
// grid barrier state
__device__ unsigned g_bar_arrive = 0;
__device__ unsigned g_bar_gen    = 0;

// ---------------------------------------------------------------------------
// Input GEMM: C[r][j] = sum_k x[b*T+t][k] * W[k][j],  r = t*B + b,
// W = concat(w_h, w_t) along columns (j<H -> w_h, else w_t).
// 128x128 block tile, BK=8, 256 threads, 8x8 per-thread micro-tile.
// ---------------------------------------------------------------------------
__global__ __launch_bounds__(256) void xw_gemm_kernel(
    const float* __restrict__ x,
    const float* __restrict__ w_h,
    const float* __restrict__ w_t)
{
    __shared__ float As[8][132];   // k-major (transposed) A tile
    __shared__ float Bs[8][132];

    const int jb  = blockIdx.x;          // 0..15  (column block of 128)
    const int rb  = blockIdx.y;          // 0..255 (row block of 128)
    const int tid = threadIdx.x;
    const int tx  = tid % 16;
    const int ty  = tid / 16;

    const int jbase = jb * 128;
    const float* W  = (jbase < H_) ? w_h : w_t;
    const int  joff = jbase % H_;

    float acc[8][8];
    #pragma unroll
    for (int i = 0; i < 8; i++)
        #pragma unroll
        for (int j = 0; j < 8; j++) acc[i][j] = 0.f;

    const int arow = tid / 2;                 // 0..127
    const int ak   = (tid % 2) * 4;           // 0 or 4
    const int r    = rb * 128 + arow;
    const int xrow = (r % B_) * T_ + (r / B_);
    const float* aptr = x + (size_t)xrow * IN_ + ak;

    const int bk = tid / 32;                  // 0..7
    const int bj = (tid % 32) * 4;            // 0..124
    const float* bptr = W + (size_t)bk * H_ + joff + bj;

    for (int kt = 0; kt < IN_; kt += 8) {
        float4 av = *(const float4*)(aptr + kt);
        float4 bv = *(const float4*)(bptr + (size_t)kt * H_);
        __syncthreads();
        As[ak + 0][arow] = av.x;
        As[ak + 1][arow] = av.y;
        As[ak + 2][arow] = av.z;
        As[ak + 3][arow] = av.w;
        *(float4*)&Bs[bk][bj] = bv;
        __syncthreads();

        #pragma unroll
        for (int k = 0; k < 8; k++) {
            float a[8], b[8];
            #pragma unroll
            for (int i = 0; i < 8; i++) a[i] = As[k][ty * 8 + i];
            #pragma unroll
            for (int j = 0; j < 8; j++) b[j] = Bs[k][tx * 8 + j];
            #pragma unroll
            for (int i = 0; i < 8; i++)
                #pragma unroll
                for (int j = 0; j < 8; j++)
                    acc[i][j] = fmaf(a[i], b[j], acc[i][j]);
        }
    }

    #pragma unroll
    for (int i = 0; i < 8; i++) {
        int rr = rb * 128 + ty * 8 + i;
        float* cp = g_xw + (size_t)rr * (2 * H_) + jbase + tx * 8;
        *(float4*)(cp + 0) = make_float4(acc[i][0], acc[i][1], acc[i][2], acc[i][3]);
        *(float4*)(cp + 4) = make_float4(acc[i][4], acc[i][5], acc[i][6], acc[i][7]);
    }
}

// ---------------------------------------------------------------------------
// Grid-wide barrier for co-resident persistent CTAs.
// Sample generation BEFORE arriving (avoids lost-wakeup race).
// ---------------------------------------------------------------------------
__device__ __forceinline__ void grid_sync_persistent()
{
    __syncthreads();                 // all block threads done with this step
    if (threadIdx.x == 0) {
        volatile unsigned* genp = &g_bar_gen;
        unsigned my_gen = *genp;
        __threadfence();             // make this block's state writes visible
        unsigned a = atomicAdd(&g_bar_arrive, 1u);
        if (a == NBLK - 1) {
            g_bar_arrive = 0;
            __threadfence();
            atomicAdd(&g_bar_gen, 1u);   // release
        } else {
            while (*genp == my_gen) { }  // spin on L2
            __threadfence();             // acquire other blocks' writes
        }
    }
    __syncthreads();
}

// ---------------------------------------------------------------------------
// Persistent recurrent kernel: all T_*L_ = 2560 micro-steps in one launch.
// 128 blocks x 128 threads. Block owns 8 g-columns of BOTH gates.
// Thread owns 4 b-rows x 1 g x 2 gates = 8 fp32 accumulators.
// K-tiles of 64 with register-prefetch pipelining.
// ---------------------------------------------------------------------------
__global__ __launch_bounds__(128) void rhn_persistent_kernel(
    const float* __restrict__ rh_w, const float* __restrict__ rh_b,
    const float* __restrict__ rt_w, const float* __restrict__ rt_b,
    float* __restrict__ out)
{
    __shared__ float s_s[64][68];      // state tile [b][k], padded row
    __shared__ float s_w[2][8][68];    // weight tile [gate][g_local][k]

    const int tid = threadIdx.x;
    const int gq  = tid % 8;           // g within block
    const int bq  = tid / 8;           // 0..15 -> b group of 4
    const int tb  = tid / 16;          // 0..7  (load-row helper)
    const int kc  = (tid % 16) * 4;    // 0..60 (load-col helper)
    const int gb  = blockIdx.x;        // 0..127
    const int g   = gb * 8 + gq;

    const float* whbase = rh_w + (size_t)(gb * 8) * H_;
    const float* wtbase = rt_w + (size_t)(gb * 8) * H_;

    int t = 0, l = 0;
    for (int step = 0; step < T_ * L_; step++) {
        const int pin = step & 1;
        const float* scur = g_state[pin];
        float*       snxt = g_state[pin ^ 1];
        const float* wh = whbase + (size_t)l * H_ * H_;
        const float* wt = wtbase + (size_t)l * H_ * H_;

        float accH[4] = {0.f, 0.f, 0.f, 0.f};
        float accT[4] = {0.f, 0.f, 0.f, 0.f};

        float4 pa[8];   // prefetched state tile (8 float4 per thread)
        float4 pwv[2];  // prefetched weight rows (h-gate, t-gate)

        // prefetch k-tile 0
        #pragma unroll
        for (int i = 0; i < 8; i++)
            pa[i] = *(const float4*)(scur + (size_t)(tb + 8 * i) * H_ + kc);
        pwv[0] = *(const float4*)(wh + (size_t)tb * H_ + kc);
        pwv[1] = *(const float4*)(wt + (size_t)tb * H_ + kc);

        for (int kt = 0; kt < 16; kt++) {
            __syncthreads();   // previous tile's compute done
            #pragma unroll
            for (int i = 0; i < 8; i++)
                *(float4*)&s_s[tb + 8 * i][kc] = pa[i];
            *(float4*)&s_w[0][tb][kc] = pwv[0];
            *(float4*)&s_w[1][tb][kc] = pwv[1];
            __syncthreads();

            if (kt < 15) {   // prefetch next tile (overlaps compute)
                const int k0 = (kt + 1) * 64;
                #pragma unroll
                for (int i = 0; i < 8; i++)
                    pa[i] = *(const float4*)(scur + (size_t)(tb + 8 * i) * H_ + k0 + kc);
                pwv[0] = *(const float4*)(wh + (size_t)tb * H_ + k0 + kc);
                pwv[1] = *(const float4*)(wt + (size_t)tb * H_ + k0 + kc);
            }

            #pragma unroll
            for (int k4 = 0; k4 < 16; k4++) {
                float4 wHv = *(const float4*)&s_w[0][gq][k4 * 4];
                float4 wTv = *(const float4*)&s_w[1][gq][k4 * 4];
                #pragma unroll
                for (int i = 0; i < 4; i++) {
                    float4 sv = *(const float4*)&s_s[bq * 4 + i][k4 * 4];
                    accH[i] = fmaf(sv.x, wHv.x, accH[i]);
                    accH[i] = fmaf(sv.y, wHv.y, accH[i]);
                    accH[i] = fmaf(sv.z, wHv.z, accH[i]);
                    accH[i] = fmaf(sv.w, wHv.w, accH[i]);
                    accT[i] = fmaf(sv.x, wTv.x, accT[i]);
                    accT[i] = fmaf(sv.y, wTv.y, accT[i]);
                    accT[i] = fmaf(sv.z, wTv.z, accT[i]);
                    accT[i] = fmaf(sv.w, wTv.w, accT[i]);
                }
            }
        }

        // epilogue: bias, (layer-0 input terms), activations, highway blend
        const float bh = rh_b[l * H_ + g];
        const float bt = rt_b[l * H_ + g];

        #pragma unroll
        for (int i = 0; i < 4; i++) {
            const int b = bq * 4 + i;
            float ph = accH[i] + bh;
            float pt = accT[i] + bt;
            if (l == 0) {
                const float* xwrow = g_xw + (size_t)(t * B_ + b) * (2 * H_);
                ph += xwrow[g];
                pt += xwrow[H_ + g];
            }
            const float so = scur[(size_t)b * H_ + g];
            const float h  = tanhf(ph);
            const float tt = 1.0f / (1.0f + expf(-pt));
            const float sn = fmaf(h - so, tt, so);
            snxt[(size_t)b * H_ + g] = sn;
            if (l == L_ - 1) {
                out[((size_t)b * T_ + t) * H_ + g] = sn;
                if (t == T_ - 1)
                    out[(size_t)B_ * T_ * H_ + (size_t)b * H_ + g] = sn;
            }
        }

        // advance (t, l)
        if (++l == L_) { l = 0; ++t; }

        // grid-wide dependency: next step reads the state written above
        if (step != T_ * L_ - 1)
            grid_sync_persistent();
    }
}

// ---------------------------------------------------------------------------
extern "C" void kernel_launch(void* const* d_in, const int* in_sizes, int n_in,
                              void* d_out, int out_size)
{
    const float* input = (const float*)d_in[0];
    const float* s0    = (const float*)d_in[1];
    const float* w_h   = (const float*)d_in[2];
    const float* w_t   = (const float*)d_in[3];
    const float* rh_w  = (const float*)d_in[4];
    const float* rh_b  = (const float*)d_in[5];
    const float* rt_w  = (const float*)d_in[6];
    const float* rt_b  = (const float*)d_in[7];
    float* out = (float*)d_out;

    // initialize state buffer 0 from input s (graph node 1)
    cudaMemcpyToSymbolAsync(g_state, s0, (size_t)B_ * H_ * sizeof(float), 0,
                            cudaMemcpyDeviceToDevice);

    // precompute whx/wtx for all (t, b) (graph node 2)
    {
        dim3 grid(16, 256);
        xw_gemm_kernel<<<grid, 256>>>(input, w_h, w_t);
    }

    // all 2560 recurrent micro-steps in one persistent launch (graph node 3)
    rhn_persistent_kernel<<<NBLK, 128>>>(rh_w, rh_b, rt_w, rt_b, out);
}

// round 4
// speedup vs baseline: 1.3681x; 1.3681x over previous
#include <cuda_runtime.h>
#include <math.h>

#define B_  64
#define T_  512
#define IN_ 1024
#define H_  1024
#define L_  5

#define NBLK 128   // persistent CTAs (<=148 so all co-resident at 1 CTA/SM)
#define TPB  256   // 8 warps -> 2 per SMSP

typedef unsigned long long ull;

// Static device scratch:
// g_xw: precomputed [whx|wtx] for all (t,b), time-major: g_xw[(t*B + b)*2H + j]
__device__ float g_xw[(size_t)B_ * T_ * 2 * H_];   // 256 MB
// double-buffered recurrent state s: [2][B][H]
__device__ float g_state[2][B_ * H_];
// grid barrier state
__device__ unsigned g_bar_arrive = 0;
__device__ unsigned g_bar_gen    = 0;

// packed fp32x2 FMA (sm_103a FFMA2) — d.lo += a.lo*b.lo ; d.hi += a.hi*b.hi
__device__ __forceinline__ void ffma2(ull& d, ull a, ull b) {
    asm("fma.rn.f32x2 %0, %1, %2, %0;" : "+l"(d) : "l"(a), "l"(b));
}
__device__ __forceinline__ float f32x2_sum(ull v) {
    union { ull u; float2 f; } c; c.u = v;
    return c.f.x + c.f.y;
}

// ---------------------------------------------------------------------------
// Input GEMM: C[r][j] = sum_k x[b*T+t][k] * W[k][j],  r = t*B + b,
// W = concat(w_h, w_t) along columns. 128x128 tile, BK=8, 256 thr, 8x8 micro.
// ---------------------------------------------------------------------------
__global__ __launch_bounds__(256) void xw_gemm_kernel(
    const float* __restrict__ x,
    const float* __restrict__ w_h,
    const float* __restrict__ w_t)
{
    __shared__ float As[8][132];
    __shared__ float Bs[8][132];

    const int jb  = blockIdx.x;
    const int rb  = blockIdx.y;
    const int tid = threadIdx.x;
    const int tx  = tid % 16;
    const int ty  = tid / 16;

    const int jbase = jb * 128;
    const float* W  = (jbase < H_) ? w_h : w_t;
    const int  joff = jbase % H_;

    float acc[8][8];
    #pragma unroll
    for (int i = 0; i < 8; i++)
        #pragma unroll
        for (int j = 0; j < 8; j++) acc[i][j] = 0.f;

    const int arow = tid / 2;
    const int ak   = (tid % 2) * 4;
    const int r    = rb * 128 + arow;
    const int xrow = (r % B_) * T_ + (r / B_);
    const float* aptr = x + (size_t)xrow * IN_ + ak;

    const int bk = tid / 32;
    const int bj = (tid % 32) * 4;
    const float* bptr = W + (size_t)bk * H_ + joff + bj;

    for (int kt = 0; kt < IN_; kt += 8) {
        float4 av = *(const float4*)(aptr + kt);
        float4 bv = *(const float4*)(bptr + (size_t)kt * H_);
        __syncthreads();
        As[ak + 0][arow] = av.x;
        As[ak + 1][arow] = av.y;
        As[ak + 2][arow] = av.z;
        As[ak + 3][arow] = av.w;
        *(float4*)&Bs[bk][bj] = bv;
        __syncthreads();

        #pragma unroll
        for (int k = 0; k < 8; k++) {
            float a[8], b[8];
            #pragma unroll
            for (int i = 0; i < 8; i++) a[i] = As[k][ty * 8 + i];
            #pragma unroll
            for (int j = 0; j < 8; j++) b[j] = Bs[k][tx * 8 + j];
            #pragma unroll
            for (int i = 0; i < 8; i++)
                #pragma unroll
                for (int j = 0; j < 8; j++)
                    acc[i][j] = fmaf(a[i], b[j], acc[i][j]);
        }
    }

    #pragma unroll
    for (int i = 0; i < 8; i++) {
        int rr = rb * 128 + ty * 8 + i;
        float* cp = g_xw + (size_t)rr * (2 * H_) + jbase + tx * 8;
        *(float4*)(cp + 0) = make_float4(acc[i][0], acc[i][1], acc[i][2], acc[i][3]);
        *(float4*)(cp + 4) = make_float4(acc[i][4], acc[i][5], acc[i][6], acc[i][7]);
    }
}

// ---------------------------------------------------------------------------
// Grid-wide barrier for co-resident persistent CTAs.
// ---------------------------------------------------------------------------
__device__ __forceinline__ void grid_sync_persistent()
{
    __syncthreads();
    if (threadIdx.x == 0) {
        volatile unsigned* genp = &g_bar_gen;
        unsigned my_gen = *genp;
        __threadfence();
        unsigned a = atomicAdd(&g_bar_arrive, 1u);
        if (a == NBLK - 1) {
            g_bar_arrive = 0;
            __threadfence();
            atomicAdd(&g_bar_gen, 1u);   // release
        } else {
            while (*genp == my_gen) { }
            __threadfence();
        }
    }
    __syncthreads();
}

// ---------------------------------------------------------------------------
// Persistent recurrent kernel: all 2560 micro-steps in one launch.
// 128 blocks x 256 threads. Block owns 8 g-columns of BOTH gates.
// Thread owns 2 b-rows x 1 g x 2 gates; packed f32x2 accumulation over k-pairs.
// K-tiles of 128 with register-prefetch pipelining (8 tiles/step).
// ---------------------------------------------------------------------------
__global__ __launch_bounds__(TPB) void rhn_persistent_kernel(
    const float* __restrict__ rh_w, const float* __restrict__ rh_b,
    const float* __restrict__ rt_w, const float* __restrict__ rt_b,
    float* __restrict__ out)
{
    __shared__ float s_s[64][132];     // state tile [b][k], padded pitch
    __shared__ float s_w[2][8][132];   // weight tile [gate][g_local][k]

    const int tid = threadIdx.x;
    const int gq  = tid & 7;           // g within block (0..7)
    const int bq  = tid >> 3;          // 0..31 -> b pair {2bq, 2bq+1}
    const int b0  = 2 * bq;
    const int b1  = 2 * bq + 1;
    const int r0   = tid >> 5;         // load helper row (0..7)
    const int col4 = (tid & 31) * 4;   // load helper col (0..124)
    const int gb  = blockIdx.x;        // 0..127
    const int g   = gb * 8 + gq;

    const float* whbase = rh_w + (size_t)(gb * 8) * H_;
    const float* wtbase = rt_w + (size_t)(gb * 8) * H_;

    int t = 0, l = 0;
    for (int step = 0; step < T_ * L_; step++) {
        const int pin = step & 1;
        const float* scur = g_state[pin];
        float*       snxt = g_state[pin ^ 1];
        const float* wh = whbase + (size_t)l * H_ * H_;
        const float* wt = wtbase + (size_t)l * H_ * H_;

        ull aH0 = 0ull, aH1 = 0ull, aT0 = 0ull, aT1 = 0ull;

        float4 pa[8];    // state prefetch: rows r0+8i
        float4 pw[2];    // weight prefetch: gate i, row r0

        // prefetch k-tile 0
        #pragma unroll
        for (int i = 0; i < 8; i++)
            pa[i] = *(const float4*)(scur + (size_t)(r0 + 8 * i) * H_ + col4);
        pw[0] = *(const float4*)(wh + (size_t)r0 * H_ + col4);
        pw[1] = *(const float4*)(wt + (size_t)r0 * H_ + col4);

        for (int kt = 0; kt < 8; kt++) {
            __syncthreads();   // previous tile's compute done
            #pragma unroll
            for (int i = 0; i < 8; i++)
                *(float4*)&s_s[r0 + 8 * i][col4] = pa[i];
            *(float4*)&s_w[0][r0][col4] = pw[0];
            *(float4*)&s_w[1][r0][col4] = pw[1];
            __syncthreads();

            if (kt < 7) {   // prefetch next tile (overlaps compute)
                const int k0 = (kt + 1) * 128 + col4;
                #pragma unroll
                for (int i = 0; i < 8; i++)
                    pa[i] = *(const float4*)(scur + (size_t)(r0 + 8 * i) * H_ + k0);
                pw[0] = *(const float4*)(wh + (size_t)r0 * H_ + k0);
                pw[1] = *(const float4*)(wt + (size_t)r0 * H_ + k0);
            }

            const float* sb0 = &s_s[b0][0];
            const float* sb1 = &s_s[b1][0];
            const float* wH  = &s_w[0][gq][0];
            const float* wT  = &s_w[1][gq][0];

            #pragma unroll
            for (int k4 = 0; k4 < 32; k4++) {
                ulonglong2 sv0 = *(const ulonglong2*)(sb0 + k4 * 4);
                ulonglong2 sv1 = *(const ulonglong2*)(sb1 + k4 * 4);
                ulonglong2 wHv = *(const ulonglong2*)(wH + k4 * 4);
                ulonglong2 wTv = *(const ulonglong2*)(wT + k4 * 4);
                ffma2(aH0, sv0.x, wHv.x);
                ffma2(aH1, sv1.x, wHv.x);
                ffma2(aT0, sv0.x, wTv.x);
                ffma2(aT1, sv1.x, wTv.x);
                ffma2(aH0, sv0.y, wHv.y);
                ffma2(aH1, sv1.y, wHv.y);
                ffma2(aT0, sv0.y, wTv.y);
                ffma2(aT1, sv1.y, wTv.y);
            }
        }

        // epilogue: bias, (layer-0 input terms), activations, highway blend
        const float bh = rh_b[l * H_ + g];
        const float bt = rt_b[l * H_ + g];

        float ph0 = f32x2_sum(aH0) + bh;
        float ph1 = f32x2_sum(aH1) + bh;
        float pt0 = f32x2_sum(aT0) + bt;
        float pt1 = f32x2_sum(aT1) + bt;

        if (l == 0) {
            const float* xw0 = g_xw + (size_t)(t * B_ + b0) * (2 * H_);
            const float* xw1 = g_xw + (size_t)(t * B_ + b1) * (2 * H_);
            ph0 += xw0[g];       pt0 += xw0[H_ + g];
            ph1 += xw1[g];       pt1 += xw1[H_ + g];
        }

        const float so0 = scur[(size_t)b0 * H_ + g];
        const float so1 = scur[(size_t)b1 * H_ + g];
        const float h0  = tanhf(ph0);
        const float h1  = tanhf(ph1);
        const float tt0 = 1.0f / (1.0f + expf(-pt0));
        const float tt1 = 1.0f / (1.0f + expf(-pt1));
        const float sn0 = fmaf(h0 - so0, tt0, so0);
        const float sn1 = fmaf(h1 - so1, tt1, so1);
        snxt[(size_t)b0 * H_ + g] = sn0;
        snxt[(size_t)b1 * H_ + g] = sn1;
        if (l == L_ - 1) {
            out[((size_t)b0 * T_ + t) * H_ + g] = sn0;
            out[((size_t)b1 * T_ + t) * H_ + g] = sn1;
            if (t == T_ - 1) {
                out[(size_t)B_ * T_ * H_ + (size_t)b0 * H_ + g] = sn0;
                out[(size_t)B_ * T_ * H_ + (size_t)b1 * H_ + g] = sn1;
            }
        }

        if (++l == L_) { l = 0; ++t; }

        if (step != T_ * L_ - 1)
            grid_sync_persistent();
    }
}

// ---------------------------------------------------------------------------
extern "C" void kernel_launch(void* const* d_in, const int* in_sizes, int n_in,
                              void* d_out, int out_size)
{
    const float* input = (const float*)d_in[0];
    const float* s0    = (const float*)d_in[1];
    const float* w_h   = (const float*)d_in[2];
    const float* w_t   = (const float*)d_in[3];
    const float* rh_w  = (const float*)d_in[4];
    const float* rh_b  = (const float*)d_in[5];
    const float* rt_w  = (const float*)d_in[6];
    const float* rt_b  = (const float*)d_in[7];
    float* out = (float*)d_out;

    // initialize state buffer 0 from input s
    cudaMemcpyToSymbolAsync(g_state, s0, (size_t)B_ * H_ * sizeof(float), 0,
                            cudaMemcpyDeviceToDevice);

    // precompute whx/wtx for all (t, b)
    {
        dim3 grid(16, 256);
        xw_gemm_kernel<<<grid, 256>>>(input, w_h, w_t);
    }

    // all 2560 recurrent micro-steps in one persistent launch
    rhn_persistent_kernel<<<NBLK, TPB>>>(rh_w, rh_b, rt_w, rt_b, out);
}